// round 2
// baseline (speedup 1.0000x reference)
#include <cuda_runtime.h>
#include <cuda_bf16.h>

#define NCLASS 100
#define NFEAT  64
#define GROUPS 4
#define TPB    (GROUPS * 64)
#define CP     (NCLASS * NFEAT)   // 6400

// Global scratch (allocation-free rule: __device__ globals)
__device__ float        g_s[CP];
__device__ float        g_ss[CP];
__device__ unsigned int g_cnt[NCLASS];

__global__ void zero_kernel() {
    int i = blockIdx.x * blockDim.x + threadIdx.x;
    if (i < CP) { g_s[i] = 0.f; g_ss[i] = 0.f; }
    if (i < NCLASS) g_cnt[i] = 0u;
}

// Each 64-thread group owns a private smem copy of s[100][64] and ss[100][64].
// Thread p of a group exclusively owns feature column p -> no races, no atomics
// in the hot loop. Rows are read fully coalesced (64 x 4B = one 256B row).
__global__ void __launch_bounds__(TPB, 1)
accum_kernel(const float* __restrict__ x, const int* __restrict__ t, int nrows) {
    extern __shared__ float smem[];
    // layout: [GROUPS][CP] s  |  [GROUPS][CP] ss  |  cnt[NCLASS]
    const int group = threadIdx.x >> 6;
    const int p     = threadIdx.x & 63;
    float* s_arr  = smem + group * CP;
    float* ss_arr = smem + GROUPS * CP + group * CP;
    unsigned int* cnt = (unsigned int*)(smem + 2 * GROUPS * CP);

    for (int i = threadIdx.x; i < 2 * GROUPS * CP; i += TPB) smem[i] = 0.f;
    for (int i = threadIdx.x; i < NCLASS; i += TPB) cnt[i] = 0u;
    __syncthreads();

    const int G      = blockIdx.x * GROUPS + group;
    const int stride = gridDim.x * GROUPS;

    #pragma unroll 4
    for (int r = G; r < nrows; r += stride) {
        const int c = __ldg(&t[r]);                  // int32 class id
        const float v = __ldg(&x[r * NFEAT + p]);    // r*64 < 2^27, int math safe
        const int idx = c * NFEAT + p;
        s_arr[idx]  += v;
        ss_arr[idx] += v * v;
        if (p == 0) atomicAdd(&cnt[c], 1u);
    }
    __syncthreads();

    // Reduce the 4 group copies and flush to global scratch.
    for (int i = threadIdx.x; i < CP; i += TPB) {
        float ts = 0.f, tss = 0.f;
        #pragma unroll
        for (int g = 0; g < GROUPS; g++) {
            ts  += smem[g * CP + i];
            tss += smem[GROUPS * CP + g * CP + i];
        }
        atomicAdd(&g_s[i],  ts);
        atomicAdd(&g_ss[i], tss);
    }
    for (int i = threadIdx.x; i < NCLASS; i += TPB)
        atomicAdd(&g_cnt[i], cnt[i]);
}

__global__ void final_kernel(float* __restrict__ out) {
    __shared__ double red[256];
    double acc = 0.0;
    for (int i = threadIdx.x; i < CP; i += 256) {
        const int c = i / NFEAT;
        const double n  = (double)g_cnt[c];
        const double s  = (double)g_s[i];
        const double ss = (double)g_ss[i];
        acc += (ss - s * s / n) / (n - 1.0);
    }
    red[threadIdx.x] = acc;
    __syncthreads();
    #pragma unroll
    for (int off = 128; off > 0; off >>= 1) {
        if ((int)threadIdx.x < off) red[threadIdx.x] += red[threadIdx.x + off];
        __syncthreads();
    }
    if (threadIdx.x == 0) out[0] = (float)(red[0] / (double)NCLASS);
}

extern "C" void kernel_launch(void* const* d_in, const int* in_sizes, int n_in,
                              void* d_out, int out_size) {
    const float* x = (const float*)d_in[0];   // (N, 64) fp32
    const int*   t = (const int*)d_in[1];     // (N,)    int32 (jax x64 disabled)
    const int nrows = in_sizes[0] / NFEAT;
    float* out = (float*)d_out;

    int nsm = 148;
    cudaDeviceGetAttribute(&nsm, cudaDevAttrMultiProcessorCount, 0);

    const size_t smem_bytes = (size_t)(2 * GROUPS * CP) * sizeof(float)
                            + (size_t)NCLASS * sizeof(unsigned int);
    cudaFuncSetAttribute(accum_kernel, cudaFuncAttributeMaxDynamicSharedMemorySize,
                         (int)smem_bytes);

    zero_kernel<<<(CP + 255) / 256, 256>>>();
    accum_kernel<<<nsm, TPB, smem_bytes>>>(x, t, nrows);
    final_kernel<<<1, 256>>>(out);
}

// round 4
// speedup vs baseline: 7.0385x; 7.0385x over previous
#include <cuda_runtime.h>
#include <cuda_bf16.h>

#define NCLASS 100
#define NFEAT  64
#define GROUPS 4
#define TPB    256
#define CP     (NCLASS * NFEAT)   // 6400
#define BATCH  16

// Global scratch (allocation-free rule: __device__ globals)
__device__ float2       g_acc[CP];     // {sum, sumsq}
__device__ unsigned int g_cnt[NCLASS];

__global__ void zero_kernel() {
    int i = blockIdx.x * blockDim.x + threadIdx.x;
    if (i < CP) g_acc[i] = make_float2(0.f, 0.f);
    if (i < NCLASS) g_cnt[i] = 0u;
}

// 64-thread group owns one private smem copy of float2 acc[100][64].
// Thread p exclusively owns feature column p -> race-free plain RMW.
// Rows are processed in contiguous BATCH-row chunks: (c,v) for the whole
// chunk are prefetched into registers (double-buffered) so 32 LDGs are in
// flight while the previous chunk's smem accumulation chain runs.
__global__ void __launch_bounds__(TPB, 1)
accum_kernel(const float* __restrict__ x, const int* __restrict__ t, int nrows) {
    extern __shared__ float2 smem[];
    const int group = threadIdx.x >> 6;
    const int p     = threadIdx.x & 63;
    float2* acc = smem + group * CP;
    unsigned int* cnt = (unsigned int*)(smem + GROUPS * CP);

    for (int i = threadIdx.x; i < GROUPS * CP; i += TPB) smem[i] = make_float2(0.f, 0.f);
    for (int i = threadIdx.x; i < NCLASS; i += TPB) cnt[i] = 0u;
    __syncthreads();

    const int gid     = blockIdx.x * GROUPS + group;
    const int ngroups = gridDim.x * GROUPS;
    const int nchunks = (nrows + BATCH - 1) / BATCH;

    int cs[BATCH], cs2[BATCH];
    float vs[BATCH], vs2[BATCH];

    auto load_chunk = [&](int ci, int* c, float* v) {
        const int r0 = ci * BATCH;
        if (r0 + BATCH <= nrows) {
            #pragma unroll
            for (int b = 0; b < BATCH; b++) {
                const int r = r0 + b;
                c[b] = __ldcs(t + r);
                v[b] = __ldcs(x + (size_t)r * NFEAT + p);
            }
        } else {
            #pragma unroll
            for (int b = 0; b < BATCH; b++) {
                const int r = r0 + b;
                const bool ok = r < nrows;
                c[b] = ok ? __ldcs(t + r) : 0;
                v[b] = ok ? __ldcs(x + (size_t)r * NFEAT + p) : 0.f;
            }
        }
    };

    auto accum_chunk = [&](int ci, const int* c, const float* v) {
        const int r0 = ci * BATCH;
        #pragma unroll
        for (int b = 0; b < BATCH; b++) {
            const int idx = c[b] * NFEAT + p;
            float2 a = acc[idx];
            a.x += v[b];
            a.y = fmaf(v[b], v[b], a.y);
            acc[idx] = a;
            if (p == 0 && r0 + b < nrows) atomicAdd(&cnt[c[b]], 1u);
        }
    };

    int ci = gid;
    if (ci < nchunks) {
        load_chunk(ci, cs, vs);
        while (true) {
            const int cn = ci + ngroups;
            if (cn < nchunks) {
                load_chunk(cn, cs2, vs2);          // LDGs in flight...
                accum_chunk(ci, cs, vs);           // ...while smem chain runs
                #pragma unroll
                for (int b = 0; b < BATCH; b++) { cs[b] = cs2[b]; vs[b] = vs2[b]; }
                ci = cn;
            } else {
                accum_chunk(ci, cs, vs);
                break;
            }
        }
    }
    __syncthreads();

    // Reduce the 4 group copies and flush to global scratch.
    for (int i = threadIdx.x; i < CP; i += TPB) {
        float ts = 0.f, tss = 0.f;
        #pragma unroll
        for (int g = 0; g < GROUPS; g++) {
            ts  += smem[g * CP + i].x;
            tss += smem[g * CP + i].y;
        }
        atomicAdd(&g_acc[i].x, ts);
        atomicAdd(&g_acc[i].y, tss);
    }
    for (int i = threadIdx.x; i < NCLASS; i += TPB)
        atomicAdd(&g_cnt[i], cnt[i]);
}

__global__ void final_kernel(float* __restrict__ out) {
    __shared__ double red[256];
    double accd = 0.0;
    for (int i = threadIdx.x; i < CP; i += 256) {
        const int c = i / NFEAT;
        const double n  = (double)g_cnt[c];
        const double s  = (double)g_acc[i].x;
        const double ss = (double)g_acc[i].y;
        accd += (ss - s * s / n) / (n - 1.0);
    }
    red[threadIdx.x] = accd;
    __syncthreads();
    #pragma unroll
    for (int off = 128; off > 0; off >>= 1) {
        if ((int)threadIdx.x < off) red[threadIdx.x] += red[threadIdx.x + off];
        __syncthreads();
    }
    if (threadIdx.x == 0) out[0] = (float)(red[0] / (double)NCLASS);
}

extern "C" void kernel_launch(void* const* d_in, const int* in_sizes, int n_in,
                              void* d_out, int out_size) {
    const float* x = (const float*)d_in[0];   // (N, 64) fp32
    const int*   t = (const int*)d_in[1];     // (N,)    int32
    const int nrows = in_sizes[0] / NFEAT;
    float* out = (float*)d_out;

    int nsm = 148;
    cudaDeviceGetAttribute(&nsm, cudaDevAttrMultiProcessorCount, 0);

    const size_t smem_bytes = (size_t)GROUPS * CP * sizeof(float2)
                            + (size_t)NCLASS * sizeof(unsigned int);
    cudaFuncSetAttribute(accum_kernel, cudaFuncAttributeMaxDynamicSharedMemorySize,
                         (int)smem_bytes);

    zero_kernel<<<(CP + 255) / 256, 256>>>();
    accum_kernel<<<nsm, TPB, smem_bytes>>>(x, t, nrows);
    final_kernel<<<1, 256>>>(out);
}

// round 5
// speedup vs baseline: 7.1985x; 1.0227x over previous
#include <cuda_runtime.h>
#include <cuda_bf16.h>

#define NCLASS 100
#define NFEAT  64
#define GROUPS 4
#define TPB    256
#define CP     (NCLASS * NFEAT)   // 6400
#define BATCH  16

// Global scratch (allocation-free rule: __device__ globals)
__device__ float2       g_acc[CP];     // {sum, sumsq}
__device__ unsigned int g_cnt[NCLASS];

__global__ void zero_kernel() {
    int i = blockIdx.x * blockDim.x + threadIdx.x;
    if (i < CP) g_acc[i] = make_float2(0.f, 0.f);
    if (i < NCLASS) g_cnt[i] = 0u;
}

// 64-thread group owns a private smem copy of float2 acc[100][64].
// Thread p exclusively owns feature column p -> race-free plain RMW.
// Per 16-row chunk: lanes 0-15 of each warp load t coalesced (one 64B LDG),
// warp 0 of the group histograms counts with ONE spread-address smem atomic
// (not one serialized single-lane atomic per row), and class ids are
// shfl-broadcast into registers BEFORE the RMW loop so neither SHFL nor
// ATOMS latency sits on the LDS->FADD->STS critical chain.
__global__ void __launch_bounds__(TPB, 1)
accum_kernel(const float* __restrict__ x, const int* __restrict__ t, int nrows) {
    extern __shared__ float2 smem[];
    const int group = threadIdx.x >> 6;
    const int p     = threadIdx.x & 63;
    const int w     = (threadIdx.x >> 5) & 1;  // warp within group
    const int l     = threadIdx.x & 31;        // lane
    float2* acc = smem + group * CP;
    unsigned int* cnt = (unsigned int*)(smem + GROUPS * CP);

    for (int i = threadIdx.x; i < GROUPS * CP; i += TPB) smem[i] = make_float2(0.f, 0.f);
    for (int i = threadIdx.x; i < NCLASS; i += TPB) cnt[i] = 0u;
    __syncthreads();

    const int gid     = blockIdx.x * GROUPS + group;
    const int ngroups = gridDim.x * GROUPS;
    const int nchunks = (nrows + BATCH - 1) / BATCH;

    float vs[BATCH], vs2[BATCH];
    int myc, myc2;

    // Issue all LDGs for chunk ci; histogram this chunk's counts (warp 0 only).
    auto load_chunk = [&](int ci, int& c_lane, float* v) {
        const int r0 = ci * BATCH;
        const int nv = min(BATCH, nrows - r0);
        c_lane = 0;
        if (l < nv) c_lane = __ldcs(t + r0 + l);          // one 64B coalesced LDG
        if (w == 0 && l < nv) atomicAdd(&cnt[c_lane], 1u); // spread-addr ATOMS, 1/chunk
        if (nv == BATCH) {
            #pragma unroll
            for (int b = 0; b < BATCH; b++)
                v[b] = __ldcs(x + (size_t)(r0 + b) * NFEAT + p);
        } else {
            #pragma unroll
            for (int b = 0; b < BATCH; b++)
                v[b] = (b < nv) ? __ldcs(x + (size_t)(r0 + b) * NFEAT + p) : 0.f;
        }
    };

    // Accumulate chunk: broadcast classes first, then tight RMW chain.
    auto accum_chunk = [&](int c_lane, const float* v) {
        int carr[BATCH];
        #pragma unroll
        for (int b = 0; b < BATCH; b++)
            carr[b] = __shfl_sync(0xffffffffu, c_lane, b);
        #pragma unroll
        for (int b = 0; b < BATCH; b++) {
            const int idx = carr[b] * NFEAT + p;
            float2 a = acc[idx];
            a.x += v[b];
            a.y = fmaf(v[b], v[b], a.y);
            acc[idx] = a;   // padded rows: v=0, c=0 -> adds zero, harmless
        }
    };

    int ci = gid;
    if (ci < nchunks) {
        load_chunk(ci, myc, vs);
        while (true) {
            const int cn = ci + ngroups;
            if (cn < nchunks) {
                load_chunk(cn, myc2, vs2);   // LDGs in flight...
                accum_chunk(myc, vs);        // ...while smem chain runs
                myc = myc2;
                #pragma unroll
                for (int b = 0; b < BATCH; b++) vs[b] = vs2[b];
                ci = cn;
            } else {
                accum_chunk(myc, vs);
                break;
            }
        }
    }
    __syncthreads();

    // Reduce the 4 group copies and flush to global scratch.
    for (int i = threadIdx.x; i < CP; i += TPB) {
        float ts = 0.f, tss = 0.f;
        #pragma unroll
        for (int g = 0; g < GROUPS; g++) {
            ts  += smem[g * CP + i].x;
            tss += smem[g * CP + i].y;
        }
        atomicAdd(&g_acc[i].x, ts);
        atomicAdd(&g_acc[i].y, tss);
    }
    for (int i = threadIdx.x; i < NCLASS; i += TPB)
        atomicAdd(&g_cnt[i], cnt[i]);
}

__global__ void final_kernel(float* __restrict__ out) {
    __shared__ double red[256];
    double accd = 0.0;
    for (int i = threadIdx.x; i < CP; i += 256) {
        const int c = i / NFEAT;
        const double n  = (double)g_cnt[c];
        const double s  = (double)g_acc[i].x;
        const double ss = (double)g_acc[i].y;
        accd += (ss - s * s / n) / (n - 1.0);
    }
    red[threadIdx.x] = accd;
    __syncthreads();
    #pragma unroll
    for (int off = 128; off > 0; off >>= 1) {
        if ((int)threadIdx.x < off) red[threadIdx.x] += red[threadIdx.x + off];
        __syncthreads();
    }
    if (threadIdx.x == 0) out[0] = (float)(red[0] / (double)NCLASS);
}

extern "C" void kernel_launch(void* const* d_in, const int* in_sizes, int n_in,
                              void* d_out, int out_size) {
    const float* x = (const float*)d_in[0];   // (N, 64) fp32
    const int*   t = (const int*)d_in[1];     // (N,)    int32
    const int nrows = in_sizes[0] / NFEAT;
    float* out = (float*)d_out;

    int nsm = 148;
    cudaDeviceGetAttribute(&nsm, cudaDevAttrMultiProcessorCount, 0);

    const size_t smem_bytes = (size_t)GROUPS * CP * sizeof(float2)
                            + (size_t)NCLASS * sizeof(unsigned int);
    cudaFuncSetAttribute(accum_kernel, cudaFuncAttributeMaxDynamicSharedMemorySize,
                         (int)smem_bytes);

    zero_kernel<<<(CP + 255) / 256, 256>>>();
    accum_kernel<<<nsm, TPB, smem_bytes>>>(x, t, nrows);
    final_kernel<<<1, 256>>>(out);
}

// round 6
// speedup vs baseline: 7.3424x; 1.0200x over previous
#include <cuda_runtime.h>
#include <cuda_bf16.h>

#define NCLASS 100
#define NCPAD  101               // +1 dummy class for duplicate-redirect
#define NFEAT  64
#define GROUPS 4
#define TPB    256
#define CP     (NCLASS * NFEAT)  // 6400 (global scratch, real classes only)
#define CPP    (NCPAD * NFEAT)   // 6464 (smem, padded)
#define BATCH  16

__device__ float2       g_acc[CP];
__device__ unsigned int g_cnt[NCLASS];

__global__ void zero_kernel() {
    int i = blockIdx.x * blockDim.x + threadIdx.x;
    if (i < CP) g_acc[i] = make_float2(0.f, 0.f);
    if (i < NCLASS) g_cnt[i] = 0u;
}

// 64-thread group owns a private smem float2 acc[101][64]; thread p owns
// column p. Rows are accumulated in PAIRS: duplicate classes within a pair
// are merged in registers and the duplicate's RMW is redirected to the dummy
// class 100 -> the two RMW addresses are provably distinct, so both LDS can
// issue back-to-back and their latencies overlap (breaks the 38-cyc/row
// serialized LDS->FADD->STS aliasing chain down to ~20 cyc/row).
__global__ void __launch_bounds__(TPB, 1)
accum_kernel(const float* __restrict__ x, const int* __restrict__ t, int nrows) {
    extern __shared__ float2 smem[];
    const int group = threadIdx.x >> 6;
    const int p     = threadIdx.x & 63;
    const int w     = (threadIdx.x >> 5) & 1;
    const int l     = threadIdx.x & 31;
    float2* acc = smem + group * CPP;
    unsigned int* cnt = (unsigned int*)(smem + GROUPS * CPP);

    for (int i = threadIdx.x; i < GROUPS * CPP; i += TPB) smem[i] = make_float2(0.f, 0.f);
    for (int i = threadIdx.x; i < NCLASS; i += TPB) cnt[i] = 0u;
    __syncthreads();

    const int gid     = blockIdx.x * GROUPS + group;
    const int ngroups = gridDim.x * GROUPS;
    const int nchunks = (nrows + BATCH - 1) / BATCH;

    float vs[BATCH], vs2[BATCH];
    int myc, myc2;

    auto load_chunk = [&](int ci, int& c_lane, float* v) {
        const int r0 = ci * BATCH;
        const int nv = min(BATCH, nrows - r0);
        c_lane = 0;
        if (l < nv) c_lane = __ldcs(t + r0 + l);           // one 64B coalesced LDG
        if (w == 0 && l < nv) atomicAdd(&cnt[c_lane], 1u); // spread-addr ATOMS, 1/chunk
        if (nv == BATCH) {
            #pragma unroll
            for (int b = 0; b < BATCH; b++)
                v[b] = __ldcs(x + (size_t)(r0 + b) * NFEAT + p);
        } else {
            #pragma unroll
            for (int b = 0; b < BATCH; b++)
                v[b] = (b < nv) ? __ldcs(x + (size_t)(r0 + b) * NFEAT + p) : 0.f;
        }
    };

    auto accum_chunk = [&](int c_lane, const float* v) {
        int carr[BATCH];
        #pragma unroll
        for (int b = 0; b < BATCH; b++)
            carr[b] = __shfl_sync(0xffffffffu, c_lane, b);
        #pragma unroll
        for (int b = 0; b < BATCH; b += 2) {
            const float v0 = v[b], v1 = v[b + 1];
            const bool dup = (carr[b] == carr[b + 1]);
            const int idx0 = carr[b] * NFEAT + p;
            const int idx1 = (dup ? NCLASS : carr[b + 1]) * NFEAT + p; // dummy if dup
            const float q1  = v1 * v1;
            const float s0  = v0 + (dup ? v1 : 0.f);
            const float q0  = fmaf(v0, v0, dup ? q1 : 0.f);
            const float s1  = dup ? 0.f : v1;
            const float q1k = dup ? 0.f : q1;
            // idx0 != idx1 always -> batch both RMWs, LDS latencies overlap
            float2 a0 = acc[idx0];
            float2 a1 = acc[idx1];
            a0.x += s0;  a0.y += q0;
            a1.x += s1;  a1.y += q1k;
            acc[idx0] = a0;
            acc[idx1] = a1;
        }
    };

    int ci = gid;
    if (ci < nchunks) {
        load_chunk(ci, myc, vs);
        while (true) {
            const int cn = ci + ngroups;
            if (cn < nchunks) {
                load_chunk(cn, myc2, vs2);   // LDGs in flight...
                accum_chunk(myc, vs);        // ...while smem RMWs run
                myc = myc2;
                #pragma unroll
                for (int b = 0; b < BATCH; b++) vs[b] = vs2[b];
                ci = cn;
            } else {
                accum_chunk(myc, vs);
                break;
            }
        }
    }
    __syncthreads();

    // Reduce the 4 group copies (real classes only) and flush to global.
    for (int i = threadIdx.x; i < CP; i += TPB) {
        float ts = 0.f, tss = 0.f;
        #pragma unroll
        for (int g = 0; g < GROUPS; g++) {
            ts  += smem[g * CPP + i].x;
            tss += smem[g * CPP + i].y;
        }
        atomicAdd(&g_acc[i].x, ts);
        atomicAdd(&g_acc[i].y, tss);
    }
    for (int i = threadIdx.x; i < NCLASS; i += TPB)
        atomicAdd(&g_cnt[i], cnt[i]);
}

__global__ void final_kernel(float* __restrict__ out) {
    __shared__ double red[256];
    double accd = 0.0;
    for (int i = threadIdx.x; i < CP; i += 256) {
        const int c = i / NFEAT;
        const double n  = (double)g_cnt[c];
        const double s  = (double)g_acc[i].x;
        const double ss = (double)g_acc[i].y;
        accd += (ss - s * s / n) / (n - 1.0);
    }
    red[threadIdx.x] = accd;
    __syncthreads();
    #pragma unroll
    for (int off = 128; off > 0; off >>= 1) {
        if ((int)threadIdx.x < off) red[threadIdx.x] += red[threadIdx.x + off];
        __syncthreads();
    }
    if (threadIdx.x == 0) out[0] = (float)(red[0] / (double)NCLASS);
}

extern "C" void kernel_launch(void* const* d_in, const int* in_sizes, int n_in,
                              void* d_out, int out_size) {
    const float* x = (const float*)d_in[0];   // (N, 64) fp32
    const int*   t = (const int*)d_in[1];     // (N,)    int32
    const int nrows = in_sizes[0] / NFEAT;
    float* out = (float*)d_out;

    int nsm = 148;
    cudaDeviceGetAttribute(&nsm, cudaDevAttrMultiProcessorCount, 0);

    const size_t smem_bytes = (size_t)GROUPS * CPP * sizeof(float2)
                            + (size_t)NCLASS * sizeof(unsigned int);
    cudaFuncSetAttribute(accum_kernel, cudaFuncAttributeMaxDynamicSharedMemorySize,
                         (int)smem_bytes);

    zero_kernel<<<(CP + 255) / 256, 256>>>();
    accum_kernel<<<nsm, TPB, smem_bytes>>>(x, t, nrows);
    final_kernel<<<1, 256>>>(out);
}